// round 2
// baseline (speedup 1.0000x reference)
#include <cuda_runtime.h>
#include <cstdint>

#define BB 256
#define NN 512
#define DD 6
#define FF 128
#define MAXDEG 6
#define BN (BB * NN)

#define TM 128         // node rows per GEMM tile
#define KC 64          // K chunk
#define SSTR 136       // smem row stride (floats), multiple of 4, padded

// Scratch (device globals: allocation-free rule)
__device__ float g_summed[BN * FF];          // 64 MB
__device__ int   g_list[MAXDEG * BN];        // 3 MB
__device__ int   g_cnt[MAXDEG];

// ---------- packed f32x2 helpers ----------
__device__ __forceinline__ unsigned long long pk2(float lo, float hi) {
    unsigned long long r;
    asm("mov.b64 %0, {%1, %2};" : "=l"(r) : "f"(lo), "f"(hi));
    return r;
}
__device__ __forceinline__ void fma2(unsigned long long& d,
                                     unsigned long long a,
                                     unsigned long long b) {
    asm("fma.rn.f32x2 %0, %1, %2, %0;" : "+l"(d) : "l"(a), "l"(b));
}
__device__ __forceinline__ void unpk2(unsigned long long v, float& lo, float& hi) {
    asm("mov.b64 {%0, %1}, %2;" : "=f"(lo), "=f"(hi) : "l"(v));
}

// ---------- kernel 0: zero counters ----------
__global__ void k_zero() {
    if (threadIdx.x < MAXDEG) g_cnt[threadIdx.x] = 0;
}

// ---------- kernel 1: gather + sum + degree bucketing ----------
// one warp per node; lane handles 4 floats (float4)
// edges are int32 (harness dtype map has no int64; jax x64-off coerces).
__global__ void k_gather(const float* __restrict__ atoms,
                         const int* __restrict__ edges) {
    int node = blockIdx.x * blockDim.y + threadIdx.y;
    int lane = threadIdx.x;

    const float4* A = reinterpret_cast<const float4*>(atoms);
    float4 acc = A[node * (FF / 4) + lane];             // self row
    int base = (node >> 9) << 9;                        // b * N (N = 512)

    int deg = 0;
#pragma unroll
    for (int s = 0; s < DD; s++) {
        int e = edges[node * DD + s];
        if (e >= 0 && e < NN) {                         // -1 = padding; bound-guarded
            deg++;
            float4 v = A[(base + e) * (FF / 4) + lane];
            acc.x += v.x; acc.y += v.y; acc.z += v.z; acc.w += v.w;
        }
    }
    reinterpret_cast<float4*>(g_summed)[node * (FF / 4) + lane] = acc;

    if (lane == 0 && deg < MAXDEG) {
        int pos = atomicAdd(&g_cnt[deg], 1);
        g_list[deg * BN + pos] = node;
    }
}

// ---------- kernel 2: per-degree SGEMM, 128x128 tile, f32x2 FMA ----------
// grid: (BN/TM, MAXDEG), block: 256 threads (16x16), 8x8 outputs/thread
__global__ __launch_bounds__(256, 2)
void k_gemm(const float* __restrict__ W,
            const float* __restrict__ bias,
            float* __restrict__ out) {
    const int d = blockIdx.y;
    const int cnt = g_cnt[d];
    const int tileBase = blockIdx.x * TM;
    if (tileBase >= cnt) return;

    extern __shared__ float sm[];
    float* Ss = sm;                  // [KC][SSTR]  S transposed: Ss[k][r]
    float* Ws = sm + KC * SSTR;      // [KC][SSTR]  Ws[k][j]

    __shared__ int s_node[TM];

    const int tid = threadIdx.x;
    const int tx = tid & 15;         // output col group
    const int ty = tid >> 4;         // output row group

    if (tid < TM) {
        int gi = tileBase + tid;
        s_node[tid] = g_list[d * BN + (gi < cnt ? gi : tileBase)];
    }

    unsigned long long acc[8][4];
#pragma unroll
    for (int i = 0; i < 8; i++)
#pragma unroll
        for (int j = 0; j < 4; j++) acc[i][j] = 0ULL;

    const float* Wd = W + d * FF * FF;

    for (int kk = 0; kk < FF; kk += KC) {
        __syncthreads();
        // load S chunk: Ss[k][r] = summed[node_r][kk+k]
        for (int i = tid; i < TM * (KC / 4); i += 256) {
            int r  = i & (TM - 1);
            int k4 = i >> 7;                           // 0..KC/4-1
            float4 v = reinterpret_cast<const float4*>(g_summed)
                           [s_node[r] * (FF / 4) + (kk >> 2) + k4];
            Ss[(k4 * 4 + 0) * SSTR + r] = v.x;
            Ss[(k4 * 4 + 1) * SSTR + r] = v.y;
            Ss[(k4 * 4 + 2) * SSTR + r] = v.z;
            Ss[(k4 * 4 + 3) * SSTR + r] = v.w;
        }
        // load W chunk: Ws[k][j] = W[d][kk+k][j]
        for (int i = tid; i < KC * (FF / 4); i += 256) {
            int k  = i >> 5;                           // FF/4 = 32 per row
            int j4 = i & 31;
            float4 v = reinterpret_cast<const float4*>(Wd + (kk + k) * FF)[j4];
            *reinterpret_cast<float4*>(&Ws[k * SSTR + j4 * 4]) = v;
        }
        __syncthreads();

#pragma unroll
        for (int k = 0; k < KC; k++) {
            float4 s0 = *reinterpret_cast<float4*>(&Ss[k * SSTR + ty * 8]);
            float4 s1 = *reinterpret_cast<float4*>(&Ss[k * SSTR + ty * 8 + 4]);
            float4 w0 = *reinterpret_cast<float4*>(&Ws[k * SSTR + tx * 8]);
            float4 w1 = *reinterpret_cast<float4*>(&Ws[k * SSTR + tx * 8 + 4]);

            unsigned long long wp[4];
            wp[0] = pk2(w0.x, w0.y);
            wp[1] = pk2(w0.z, w0.w);
            wp[2] = pk2(w1.x, w1.y);
            wp[3] = pk2(w1.z, w1.w);

            float sv[8] = {s0.x, s0.y, s0.z, s0.w, s1.x, s1.y, s1.z, s1.w};
#pragma unroll
            for (int i = 0; i < 8; i++) {
                unsigned long long sp = pk2(sv[i], sv[i]);
#pragma unroll
                for (int jp = 0; jp < 4; jp++) fma2(acc[i][jp], sp, wp[jp]);
            }
        }
    }

    // epilogue: bias + relu + scatter store
    float bj[8];
#pragma unroll
    for (int t = 0; t < 8; t++) bj[t] = bias[d * FF + tx * 8 + t];

#pragma unroll
    for (int i = 0; i < 8; i++) {
        int gi = tileBase + ty * 8 + i;
        if (gi < cnt) {
            int node = s_node[ty * 8 + i];
            float o[8];
#pragma unroll
            for (int jp = 0; jp < 4; jp++) unpk2(acc[i][jp], o[2 * jp], o[2 * jp + 1]);
#pragma unroll
            for (int t = 0; t < 8; t++) o[t] = fmaxf(o[t] + bj[t], 0.0f);
            float4* op = reinterpret_cast<float4*>(out + (size_t)node * FF + tx * 8);
            op[0] = make_float4(o[0], o[1], o[2], o[3]);
            op[1] = make_float4(o[4], o[5], o[6], o[7]);
        }
    }
}

extern "C" void kernel_launch(void* const* d_in, const int* in_sizes, int n_in,
                              void* d_out, int out_size) {
    const float* atoms = (const float*)d_in[0];
    const int*   edges = (const int*)d_in[1];
    const float* W     = (const float*)d_in[2];
    const float* bias  = (const float*)d_in[3];
    float*       out   = (float*)d_out;

    const int smem = 2 * KC * SSTR * sizeof(float);   // 69632 B
    cudaFuncSetAttribute(k_gemm, cudaFuncAttributeMaxDynamicSharedMemorySize, smem);

    k_zero<<<1, 32>>>();
    k_gather<<<BN / 8, dim3(32, 8)>>>(atoms, edges);
    k_gemm<<<dim3(BN / TM, MAXDEG), 256, smem>>>(W, bias, out);
}

// round 4
// speedup vs baseline: 1.4942x; 1.4942x over previous
#include <cuda_runtime.h>
#include <cuda_bf16.h>
#include <cstdint>

#define BB 256
#define NN 512
#define DD 6
#define FF 128
#define MAXDEG 6
#define BN (BB * NN)
#define TM 128
#define SSTR 136   // smem row stride in bf16 elems (128 + 8 pad)

// ---- smem byte offsets ----
#define SM_SH   0                      // Sh: 128 x SSTR bf16 (34816B)
#define SM_SL   34816
#define SM_WH   69632
#define SM_WL   104448
#define SM_NODE 139264                 // 128 ints
#define SM_BIAS 139776                 // 128 floats
#define SM_BYTES 140288

// ---- device scratch (allocation-free rule) ----
__device__ int g_list[MAXDEG * BN];
__device__ int g_cnt[MAXDEG];
__device__ __nv_bfloat16 g_wh[MAXDEG * FF * FF];   // W^T hi: [d][n][k]
__device__ __nv_bfloat16 g_wl[MAXDEG * FF * FF];   // W^T lo

__device__ __forceinline__ uint32_t smem_u32(const void* p) {
    uint32_t a;
    asm("{ .reg .u64 t; cvta.to.shared.u64 t, %1; cvt.u32.u64 %0, t; }" : "=r"(a) : "l"(p));
    return a;
}
__device__ __forceinline__ void ldm_x4(uint32_t& r0, uint32_t& r1, uint32_t& r2, uint32_t& r3,
                                       uint32_t addr) {
    asm volatile("ldmatrix.sync.aligned.m8n8.x4.shared.b16 {%0,%1,%2,%3}, [%4];"
                 : "=r"(r0), "=r"(r1), "=r"(r2), "=r"(r3) : "r"(addr));
}
__device__ __forceinline__ void mma16816(float* c, const uint32_t* a, uint32_t b0, uint32_t b1) {
    asm volatile("mma.sync.aligned.m16n8k16.row.col.f32.bf16.bf16.f32 "
                 "{%0,%1,%2,%3}, {%4,%5,%6,%7}, {%8,%9}, {%0,%1,%2,%3};"
                 : "+f"(c[0]), "+f"(c[1]), "+f"(c[2]), "+f"(c[3])
                 : "r"(a[0]), "r"(a[1]), "r"(a[2]), "r"(a[3]), "r"(b0), "r"(b1));
}

// ===================== kernel 0: zero counters =====================
__global__ void k_zero() {
    if (threadIdx.x < MAXDEG) g_cnt[threadIdx.x] = 0;
}

// ===================== kernel 1: bucket nodes by degree ============
__global__ void k_bucket(const int* __restrict__ edges) {
    __shared__ int c[MAXDEG];
    __shared__ int base[MAXDEG];
    int t = threadIdx.x;                    // 512 threads
    if (t < MAXDEG) c[t] = 0;
    __syncthreads();
    int node = blockIdx.x * 512 + t;
    int deg = 0;
#pragma unroll
    for (int s = 0; s < DD; s++) deg += (edges[node * DD + s] >= 0);
    if (deg >= MAXDEG) deg = MAXDEG - 1;
    int pos = atomicAdd(&c[deg], 1);
    __syncthreads();
    if (t < MAXDEG) base[t] = atomicAdd(&g_cnt[t], c[t]);
    __syncthreads();
    g_list[deg * BN + base[deg] + pos] = node;
}

// ===================== kernel 2: split+transpose W =================
__global__ void k_wsplit(const float* __restrict__ W) {
    int i = blockIdx.x * blockDim.x + threadIdx.x;   // < 6*128*128
    int d = i >> 14, rem = i & 16383, k = rem >> 7, n = rem & 127;
    float v = W[i];                                  // W[d][k][n]
    __nv_bfloat16 hi = __float2bfloat16(v);
    float lo = v - __bfloat162float(hi);
    int o = (d << 14) + (n << 7) + k;                // W^T[d][n][k]
    g_wh[o] = hi;
    g_wl[o] = __float2bfloat16(lo);
}

// ===================== kernel 3: fused gather + HMMA GEMM ==========
// grid (BN/TM, MAXDEG), 256 threads = 8 warps; warp w owns rows w*16..w*16+15
__global__ __launch_bounds__(256, 1)
void k_mma(const float* __restrict__ atoms,
           const int* __restrict__ edges,
           const float* __restrict__ bias,
           float* __restrict__ out) {
    const int d = blockIdx.y;
    const int cnt = g_cnt[d];
    const int tileBase = blockIdx.x * TM;
    if (tileBase >= cnt) return;

    extern __shared__ char smc[];
    const uint32_t sb = smem_u32(smc);

    const int tid = threadIdx.x;
    const int wid = tid >> 5;
    const int lid = tid & 31;

    int*   snode = (int*)(smc + SM_NODE);
    float* sbias = (float*)(smc + SM_BIAS);

    if (tid < TM) {
        int gi = tileBase + tid;
        snode[tid] = g_list[d * BN + (gi < cnt ? gi : cnt - 1)];
        sbias[tid] = bias[d * FF + tid];
    }
    __syncthreads();

    // ---- load W^T hi/lo tiles into padded smem: row n, k contiguous
    {
        const __nv_bfloat16* wh = g_wh + (d << 14);
        const __nv_bfloat16* wl = g_wl + (d << 14);
        for (int i = tid; i < FF * 16; i += 256) {
            int row = i >> 4, col = (i & 15) * 8;
            uint32_t so = (uint32_t)(row * SSTR + col) * 2;
            *(float4*)(smc + SM_WH + so) = *(const float4*)(wh + row * FF + col);
            *(float4*)(smc + SM_WL + so) = *(const float4*)(wl + row * FF + col);
        }
    }

    // ---- fused gather + sum + bf16 hi/lo split into smem
    {
        const int rr  = tid >> 3;          // 32 rows per pass
        const int c0  = (tid & 7) * 16;    // 16 cols per thread
#pragma unroll
        for (int p = 0; p < 4; p++) {
            int r = p * 32 + rr;
            int node = snode[r];
            const float4* Ap = (const float4*)(atoms + (size_t)node * FF + c0);
            float4 a0 = Ap[0], a1 = Ap[1], a2 = Ap[2], a3 = Ap[3];
            int eb = node * DD;
            int nb = (node >> 9) << 9;     // batch base (N=512)
#pragma unroll
            for (int s = 0; s < DD; s++) {
                int e = edges[eb + s];
                if (e >= 0) {
                    e = (e < NN) ? e : 0;
                    const float4* Np = (const float4*)(atoms + (size_t)(nb + e) * FF + c0);
                    float4 v0 = Np[0], v1 = Np[1], v2 = Np[2], v3 = Np[3];
                    a0.x += v0.x; a0.y += v0.y; a0.z += v0.z; a0.w += v0.w;
                    a1.x += v1.x; a1.y += v1.y; a1.z += v1.z; a1.w += v1.w;
                    a2.x += v2.x; a2.y += v2.y; a2.z += v2.z; a2.w += v2.w;
                    a3.x += v3.x; a3.y += v3.y; a3.z += v3.z; a3.w += v3.w;
                }
            }
            float vals[16] = {a0.x, a0.y, a0.z, a0.w, a1.x, a1.y, a1.z, a1.w,
                              a2.x, a2.y, a2.z, a2.w, a3.x, a3.y, a3.z, a3.w};
            uint32_t rowb = (uint32_t)(r * SSTR + c0) * 2;
#pragma unroll
            for (int j = 0; j < 8; j++) {
                float v0 = vals[2 * j], v1 = vals[2 * j + 1];
                __nv_bfloat16 h0 = __float2bfloat16(v0);
                __nv_bfloat16 h1 = __float2bfloat16(v1);
                __nv_bfloat16 l0 = __float2bfloat16(v0 - __bfloat162float(h0));
                __nv_bfloat16 l1 = __float2bfloat16(v1 - __bfloat162float(h1));
                uint32_t hp = ((uint32_t)__bfloat16_as_ushort(h1) << 16) | __bfloat16_as_ushort(h0);
                uint32_t lp = ((uint32_t)__bfloat16_as_ushort(l1) << 16) | __bfloat16_as_ushort(l0);
                *(uint32_t*)(smc + SM_SH + rowb + 4 * j) = hp;
                *(uint32_t*)(smc + SM_SL + rowb + 4 * j) = lp;
            }
        }
    }
    __syncthreads();

    // ---- warp MMA: D = Sh*Wh^T + Sh*Wl^T + Sl*Wh^T, single accumulator
    float acc[16][4];
#pragma unroll
    for (int t = 0; t < 16; t++)
#pragma unroll
        for (int q = 0; q < 4; q++) acc[t][q] = 0.f;

    const int wrow = wid * 16;
    // A ldmatrix lane address (row/col-block per lane)
    const int arow = wrow + (lid & 7) + ((lid >> 3) & 1) * 8;
    const int acol = ((lid >> 4) & 1) * 8;
    const uint32_t aoff = (uint32_t)(arow * SSTR + acol) * 2;
    // B ldmatrix lane pattern
    const int bnl  = (lid & 7) + ((lid >> 4) & 1) * 8;
    const int bcol = ((lid >> 3) & 1) * 8;

#pragma unroll
    for (int kb = 0; kb < 8; kb++) {
        const uint32_t kbyte = (uint32_t)kb * 32;   // 16 bf16
        uint32_t ah[4], al[4];
        ldm_x4(ah[0], ah[1], ah[2], ah[3], sb + SM_SH + aoff + kbyte);
        ldm_x4(al[0], al[1], al[2], al[3], sb + SM_SL + aoff + kbyte);
#pragma unroll
        for (int p = 0; p < 8; p++) {
            uint32_t boff = (uint32_t)((p * 16 + bnl) * SSTR + bcol) * 2 + kbyte;
            uint32_t bh0, bh1, bh2, bh3, bl0, bl1, bl2, bl3;
            ldm_x4(bh0, bh1, bh2, bh3, sb + SM_WH + boff);
            ldm_x4(bl0, bl1, bl2, bl3, sb + SM_WL + boff);
            mma16816(acc[2 * p],     ah, bh0, bh1);
            mma16816(acc[2 * p],     ah, bl0, bl1);
            mma16816(acc[2 * p],     al, bh0, bh1);
            mma16816(acc[2 * p + 1], ah, bh2, bh3);
            mma16816(acc[2 * p + 1], ah, bl2, bl3);
            mma16816(acc[2 * p + 1], al, bh2, bh3);
        }
    }

    // ---- epilogue: bias + relu + scatter store (float2 per tile-row)
    {
        const int r0 = wrow + (lid >> 2);
        const int r1 = r0 + 8;
        const bool ok0 = (tileBase + r0) < cnt;
        const bool ok1 = (tileBase + r1) < cnt;
        float* op0 = out + (size_t)snode[r0] * FF;
        float* op1 = out + (size_t)snode[r1] * FF;
        const int cb = (lid & 3) * 2;
#pragma unroll
        for (int t = 0; t < 16; t++) {
            int c = t * 8 + cb;
            float b0 = sbias[c], b1 = sbias[c + 1];
            if (ok0) {
                float x0 = fmaxf(acc[t][0] + b0, 0.f);
                float x1 = fmaxf(acc[t][1] + b1, 0.f);
                *(float2*)(op0 + c) = make_float2(x0, x1);
            }
            if (ok1) {
                float x2 = fmaxf(acc[t][2] + b0, 0.f);
                float x3 = fmaxf(acc[t][3] + b1, 0.f);
                *(float2*)(op1 + c) = make_float2(x2, x3);
            }
        }
    }
}

// ===================== launch =====================
extern "C" void kernel_launch(void* const* d_in, const int* in_sizes, int n_in,
                              void* d_out, int out_size) {
    const float* atoms = (const float*)d_in[0];
    const int*   edges = (const int*)d_in[1];
    const float* W     = (const float*)d_in[2];
    const float* bias  = (const float*)d_in[3];
    float*       out   = (float*)d_out;

    cudaFuncSetAttribute(k_mma, cudaFuncAttributeMaxDynamicSharedMemorySize, SM_BYTES);

    k_zero<<<1, 32>>>();
    k_bucket<<<BN / 512, 512>>>(edges);
    k_wsplit<<<(MAXDEG * FF * FF) / 256, 256>>>(W);
    k_mma<<<dim3(BN / TM, MAXDEG), 256, SM_BYTES>>>(atoms, edges, bias, out);
}

// round 5
// speedup vs baseline: 1.4992x; 1.0034x over previous
#include <cuda_runtime.h>
#include <cuda_bf16.h>
#include <cstdint>

#define BB 256
#define NN 512
#define DD 6
#define FF 128
#define MAXDEG 6
#define BN (BB * NN)
#define TM 128
#define SSTR 136   // smem row stride in bf16 elems (128 + 8 pad)

// ---- smem byte offsets ----
#define SM_SH   0                      // Sh: 128 x SSTR bf16 (34816B)
#define SM_SL   34816
#define SM_WH   69632
#define SM_WL   104448
#define SM_NODE 139264                 // 128 ints
#define SM_BIAS 139776                 // 128 floats
#define SM_BYTES 140288

// ---- device scratch (allocation-free rule) ----
__device__ int g_list[MAXDEG * BN];
__device__ int g_cnt[MAXDEG];
__device__ __nv_bfloat16 g_wh[MAXDEG * FF * FF];   // W^T hi: [d][n][k]
__device__ __nv_bfloat16 g_wl[MAXDEG * FF * FF];   // W^T lo

__device__ __forceinline__ uint32_t smem_u32(const void* p) {
    uint32_t a;
    asm("{ .reg .u64 t; cvta.to.shared.u64 t, %1; cvt.u32.u64 %0, t; }" : "=r"(a) : "l"(p));
    return a;
}
__device__ __forceinline__ void ldm_x4(uint32_t& r0, uint32_t& r1, uint32_t& r2, uint32_t& r3,
                                       uint32_t addr) {
    asm volatile("ldmatrix.sync.aligned.m8n8.x4.shared.b16 {%0,%1,%2,%3}, [%4];"
                 : "=r"(r0), "=r"(r1), "=r"(r2), "=r"(r3) : "r"(addr));
}
__device__ __forceinline__ void mma16816(float* c, const uint32_t* a, uint32_t b0, uint32_t b1) {
    asm volatile("mma.sync.aligned.m16n8k16.row.col.f32.bf16.bf16.f32 "
                 "{%0,%1,%2,%3}, {%4,%5,%6,%7}, {%8,%9}, {%0,%1,%2,%3};"
                 : "+f"(c[0]), "+f"(c[1]), "+f"(c[2]), "+f"(c[3])
                 : "r"(a[0]), "r"(a[1]), "r"(a[2]), "r"(a[3]), "r"(b0), "r"(b1));
}

// ===================== kernel 0: zero counters =====================
__global__ void k_zero() {
    if (threadIdx.x < MAXDEG) g_cnt[threadIdx.x] = 0;
}

// ===================== kernel 1: bucket nodes by degree ============
__global__ void k_bucket(const int* __restrict__ edges) {
    __shared__ int c[MAXDEG];
    __shared__ int base[MAXDEG];
    int t = threadIdx.x;                    // 512 threads
    if (t < MAXDEG) c[t] = 0;
    __syncthreads();
    int node = blockIdx.x * 512 + t;
    int deg = 0;
#pragma unroll
    for (int s = 0; s < DD; s++) deg += (edges[node * DD + s] >= 0);
    if (deg >= MAXDEG) deg = MAXDEG - 1;
    int pos = atomicAdd(&c[deg], 1);
    __syncthreads();
    if (t < MAXDEG) base[t] = atomicAdd(&g_cnt[t], c[t]);
    __syncthreads();
    g_list[deg * BN + base[deg] + pos] = node;
}

// ===================== kernel 2: split+transpose W =================
__global__ void k_wsplit(const float* __restrict__ W) {
    int i = blockIdx.x * blockDim.x + threadIdx.x;   // < 6*128*128
    int d = i >> 14, rem = i & 16383, k = rem >> 7, n = rem & 127;
    float v = W[i];                                  // W[d][k][n]
    __nv_bfloat16 hi = __float2bfloat16(v);
    float lo = v - __bfloat162float(hi);
    int o = (d << 14) + (n << 7) + k;                // W^T[d][n][k]
    g_wh[o] = hi;
    g_wl[o] = __float2bfloat16(lo);
}

// ===================== kernel 3: fused gather + HMMA GEMM ==========
// grid (BN/TM, MAXDEG), 256 threads = 8 warps; warp w owns rows w*16..w*16+15
__global__ __launch_bounds__(256, 1)
void k_mma(const float* __restrict__ atoms,
           const int* __restrict__ edges,
           const float* __restrict__ bias,
           float* __restrict__ out) {
    const int d = blockIdx.y;
    const int cnt = g_cnt[d];
    const int tileBase = blockIdx.x * TM;
    if (tileBase >= cnt) return;

    extern __shared__ char smc[];
    const uint32_t sb = smem_u32(smc);

    const int tid = threadIdx.x;
    const int wid = tid >> 5;
    const int lid = tid & 31;

    int*   snode = (int*)(smc + SM_NODE);
    float* sbias = (float*)(smc + SM_BIAS);

    if (tid < TM) {
        int gi = tileBase + tid;
        snode[tid] = g_list[d * BN + (gi < cnt ? gi : cnt - 1)];
        sbias[tid] = bias[d * FF + tid];
    }
    __syncthreads();

    // ---- load W^T hi/lo tiles into padded smem: row n, k contiguous
    {
        const __nv_bfloat16* wh = g_wh + (d << 14);
        const __nv_bfloat16* wl = g_wl + (d << 14);
        for (int i = tid; i < FF * 16; i += 256) {
            int row = i >> 4, col = (i & 15) * 8;
            uint32_t so = (uint32_t)(row * SSTR + col) * 2;
            *(float4*)(smc + SM_WH + so) = *(const float4*)(wh + row * FF + col);
            *(float4*)(smc + SM_WL + so) = *(const float4*)(wl + row * FF + col);
        }
    }

    // ---- fused gather + sum + bf16 hi/lo split into smem
    {
        const int rr  = tid >> 3;          // 32 rows per pass
        const int c0  = (tid & 7) * 16;    // 16 cols per thread
#pragma unroll
        for (int p = 0; p < 4; p++) {
            int r = p * 32 + rr;
            int node = snode[r];
            const float4* Ap = (const float4*)(atoms + (size_t)node * FF + c0);
            float4 a0 = Ap[0], a1 = Ap[1], a2 = Ap[2], a3 = Ap[3];
            int eb = node * DD;
            int nb = (node >> 9) << 9;     // batch base (N=512)
#pragma unroll
            for (int s = 0; s < DD; s++) {
                int e = edges[eb + s];
                if (e >= 0) {
                    e = (e < NN) ? e : 0;
                    const float4* Np = (const float4*)(atoms + (size_t)(nb + e) * FF + c0);
                    float4 v0 = Np[0], v1 = Np[1], v2 = Np[2], v3 = Np[3];
                    a0.x += v0.x; a0.y += v0.y; a0.z += v0.z; a0.w += v0.w;
                    a1.x += v1.x; a1.y += v1.y; a1.z += v1.z; a1.w += v1.w;
                    a2.x += v2.x; a2.y += v2.y; a2.z += v2.z; a2.w += v2.w;
                    a3.x += v3.x; a3.y += v3.y; a3.z += v3.z; a3.w += v3.w;
                }
            }
            float vals[16] = {a0.x, a0.y, a0.z, a0.w, a1.x, a1.y, a1.z, a1.w,
                              a2.x, a2.y, a2.z, a2.w, a3.x, a3.y, a3.z, a3.w};
            uint32_t rowb = (uint32_t)(r * SSTR + c0) * 2;
#pragma unroll
            for (int j = 0; j < 8; j++) {
                float v0 = vals[2 * j], v1 = vals[2 * j + 1];
                __nv_bfloat16 h0 = __float2bfloat16(v0);
                __nv_bfloat16 h1 = __float2bfloat16(v1);
                __nv_bfloat16 l0 = __float2bfloat16(v0 - __bfloat162float(h0));
                __nv_bfloat16 l1 = __float2bfloat16(v1 - __bfloat162float(h1));
                uint32_t hp = ((uint32_t)__bfloat16_as_ushort(h1) << 16) | __bfloat16_as_ushort(h0);
                uint32_t lp = ((uint32_t)__bfloat16_as_ushort(l1) << 16) | __bfloat16_as_ushort(l0);
                *(uint32_t*)(smc + SM_SH + rowb + 4 * j) = hp;
                *(uint32_t*)(smc + SM_SL + rowb + 4 * j) = lp;
            }
        }
    }
    __syncthreads();

    // ---- warp MMA: D = Sh*Wh^T + Sh*Wl^T + Sl*Wh^T, single accumulator
    float acc[16][4];
#pragma unroll
    for (int t = 0; t < 16; t++)
#pragma unroll
        for (int q = 0; q < 4; q++) acc[t][q] = 0.f;

    const int wrow = wid * 16;
    // A ldmatrix lane address (row/col-block per lane)
    const int arow = wrow + (lid & 7) + ((lid >> 3) & 1) * 8;
    const int acol = ((lid >> 4) & 1) * 8;
    const uint32_t aoff = (uint32_t)(arow * SSTR + acol) * 2;
    // B ldmatrix lane pattern
    const int bnl  = (lid & 7) + ((lid >> 4) & 1) * 8;
    const int bcol = ((lid >> 3) & 1) * 8;

#pragma unroll
    for (int kb = 0; kb < 8; kb++) {
        const uint32_t kbyte = (uint32_t)kb * 32;   // 16 bf16
        uint32_t ah[4], al[4];
        ldm_x4(ah[0], ah[1], ah[2], ah[3], sb + SM_SH + aoff + kbyte);
        ldm_x4(al[0], al[1], al[2], al[3], sb + SM_SL + aoff + kbyte);
#pragma unroll
        for (int p = 0; p < 8; p++) {
            uint32_t boff = (uint32_t)((p * 16 + bnl) * SSTR + bcol) * 2 + kbyte;
            uint32_t bh0, bh1, bh2, bh3, bl0, bl1, bl2, bl3;
            ldm_x4(bh0, bh1, bh2, bh3, sb + SM_WH + boff);
            ldm_x4(bl0, bl1, bl2, bl3, sb + SM_WL + boff);
            mma16816(acc[2 * p],     ah, bh0, bh1);
            mma16816(acc[2 * p],     ah, bl0, bl1);
            mma16816(acc[2 * p],     al, bh0, bh1);
            mma16816(acc[2 * p + 1], ah, bh2, bh3);
            mma16816(acc[2 * p + 1], ah, bl2, bl3);
            mma16816(acc[2 * p + 1], al, bh2, bh3);
        }
    }

    // ---- epilogue: bias + relu + scatter store (float2 per tile-row)
    {
        const int r0 = wrow + (lid >> 2);
        const int r1 = r0 + 8;
        const bool ok0 = (tileBase + r0) < cnt;
        const bool ok1 = (tileBase + r1) < cnt;
        float* op0 = out + (size_t)snode[r0] * FF;
        float* op1 = out + (size_t)snode[r1] * FF;
        const int cb = (lid & 3) * 2;
#pragma unroll
        for (int t = 0; t < 16; t++) {
            int c = t * 8 + cb;
            float b0 = sbias[c], b1 = sbias[c + 1];
            if (ok0) {
                float x0 = fmaxf(acc[t][0] + b0, 0.f);
                float x1 = fmaxf(acc[t][1] + b1, 0.f);
                *(float2*)(op0 + c) = make_float2(x0, x1);
            }
            if (ok1) {
                float x2 = fmaxf(acc[t][2] + b0, 0.f);
                float x3 = fmaxf(acc[t][3] + b1, 0.f);
                *(float2*)(op1 + c) = make_float2(x2, x3);
            }
        }
    }
}

// ===================== launch =====================
extern "C" void kernel_launch(void* const* d_in, const int* in_sizes, int n_in,
                              void* d_out, int out_size) {
    const float* atoms = (const float*)d_in[0];
    const int*   edges = (const int*)d_in[1];
    const float* W     = (const float*)d_in[2];
    const float* bias  = (const float*)d_in[3];
    float*       out   = (float*)d_out;

    cudaFuncSetAttribute(k_mma, cudaFuncAttributeMaxDynamicSharedMemorySize, SM_BYTES);

    k_zero<<<1, 32>>>();
    k_bucket<<<BN / 512, 512>>>(edges);
    k_wsplit<<<(MAXDEG * FF * FF) / 256, 256>>>(W);
    k_mma<<<dim3(BN / TM, MAXDEG), 256, SM_BYTES>>>(atoms, edges, bias, out);
}